// round 14
// baseline (speedup 1.0000x reference)
#include <cuda_runtime.h>
#include <cuda_bf16.h>
#include <cstdint>

// Problem constants
#define BQ 8
#define NN 4096
#define CC 768
#define EE 768
#define MM (BQ * NN)     // 32768 tokens
#define QKVD (3 * EE)    // 2304
#define KVCH 64          // kv reduction chunks per batch

// ---------------- device scratch (no allocation allowed) -------------------
__device__ __align__(128) float  g_qkv[(size_t)MM * QKVD];    // GEMM1 out fp32
__device__ __align__(128) int8_t g_aq1[(size_t)MM * CC];      // A quant level 1
__device__ __align__(128) int8_t g_aq2[(size_t)MM * CC];      // A quant level 2
__device__ __align__(128) float  g_asc[MM];                   // A row scales
__device__ __align__(128) int8_t g_bq1q[(size_t)QKVD * CC];   // w_qkv^T q1 [2304,768]
__device__ __align__(128) int8_t g_bq2q[(size_t)QKVD * CC];
__device__ __align__(128) float  g_bscq[QKVD];
__device__ __align__(128) int8_t g_bq1p[(size_t)EE * CC];     // w_proj^T q1 [768,768]
__device__ __align__(128) int8_t g_bq2p[(size_t)EE * CC];
__device__ __align__(128) float  g_bscp[EE];
__device__ float g_kvpart[KVCH * BQ * EE];
__device__ float g_kv[BQ * EE];
__device__ float g_kinv[MM];

#define QSCL2 254.0f

// ---------------------------- helpers --------------------------------------
__device__ __forceinline__ uint32_t smem_u32(const void* p) {
    uint32_t a;
    asm("{ .reg .u64 t; cvta.to.shared.u64 t, %1; cvt.u32.u64 %0, t; }"
        : "=r"(a) : "l"(p));
    return a;
}
__device__ __forceinline__ void cpa16(uint32_t dst, const void* src) {
    asm volatile("cp.async.cg.shared.global [%0], [%1], 16;" :: "r"(dst), "l"(src));
}
__device__ __forceinline__ void ldsm4(uint32_t* r, uint32_t addr) {
    asm volatile("ldmatrix.sync.aligned.m8n8.x4.shared.b16 {%0,%1,%2,%3}, [%4];"
                 : "=r"(r[0]), "=r"(r[1]), "=r"(r[2]), "=r"(r[3]) : "r"(addr));
}
__device__ __forceinline__ void mma_s8(int* d, const uint32_t* a,
                                       const uint32_t* b) {
    asm volatile(
        "mma.sync.aligned.m16n8k32.row.col.s32.s8.s8.s32 "
        "{%0,%1,%2,%3},{%4,%5,%6,%7},{%8,%9},{%0,%1,%2,%3};"
        : "+r"(d[0]), "+r"(d[1]), "+r"(d[2]), "+r"(d[3])
        : "r"(a[0]), "r"(a[1]), "r"(a[2]), "r"(a[3]), "r"(b[0]), "r"(b[1]));
}

// warp butterfly reductions: every lane gets the result; no barriers
__device__ __forceinline__ float warp_sum(float v) {
#pragma unroll
    for (int o = 16; o > 0; o >>= 1) v += __shfl_xor_sync(0xffffffffu, v, o);
    return v;
}
__device__ __forceinline__ float warp_max(float v) {
#pragma unroll
    for (int o = 16; o > 0; o >>= 1)
        v = fmaxf(v, __shfl_xor_sync(0xffffffffu, v, o));
    return v;
}

// quantize 4 values -> two char4 (levels 1 and 2)
__device__ __forceinline__ void quant4(const float* y, float inv,
                                       char4& c1, char4& c2) {
    int q1[4], q2[4];
#pragma unroll
    for (int e = 0; e < 4; e++) {
        q1[e] = __float2int_rn(y[e] * inv);
        float r = fmaf(y[e], inv, -(float)q1[e]);
        q2[e] = __float2int_rn(r * QSCL2);
    }
    c1 = make_char4((char)q1[0], (char)q1[1], (char)q1[2], (char)q1[3]);
    c2 = make_char4((char)q2[0], (char)q2[1], (char)q2[2], (char)q2[3]);
}

// ---------------------------------------------------------------------------
// Kernel 1: warp-per-token layernorm(x) + int8 2-level quant. No barriers.
// ---------------------------------------------------------------------------
__global__ __launch_bounds__(256) void k_ln_in(const float* __restrict__ x,
                                               const float* __restrict__ gam,
                                               const float* __restrict__ bet) {
    int lane = threadIdx.x & 31;
    int t = blockIdx.x * 8 + (threadIdx.x >> 5);
    const float4* row = (const float4*)(x + (size_t)t * CC);
    const float4* g4 = (const float4*)gam;
    const float4* b4 = (const float4*)bet;

    float4 v[6];
    float s = 0.f, sq = 0.f;
#pragma unroll
    for (int g = 0; g < 6; g++) {
        v[g] = row[lane + 32 * g];
        s += v[g].x + v[g].y + v[g].z + v[g].w;
        sq += v[g].x * v[g].x + v[g].y * v[g].y + v[g].z * v[g].z + v[g].w * v[g].w;
    }
    s = warp_sum(s);
    sq = warp_sum(sq);
    float mu = s * (1.0f / CC);
    float rstd = rsqrtf(sq * (1.0f / CC) - mu * mu + 1e-5f);

    float y[6][4];
    float m = 0.f;
#pragma unroll
    for (int g = 0; g < 6; g++) {
        float4 gg = g4[lane + 32 * g], bb = b4[lane + 32 * g];
        y[g][0] = (v[g].x - mu) * rstd * gg.x + bb.x;
        y[g][1] = (v[g].y - mu) * rstd * gg.y + bb.y;
        y[g][2] = (v[g].z - mu) * rstd * gg.z + bb.z;
        y[g][3] = (v[g].w - mu) * rstd * gg.w + bb.w;
#pragma unroll
        for (int e = 0; e < 4; e++) m = fmaxf(m, fabsf(y[g][e]));
    }
    m = warp_max(m);
    float sa = fmaxf(m, 1e-30f) * (1.0f / 127.0f);
    float inv = 1.0f / sa;
    if (lane == 0) g_asc[t] = sa;

    char4* d1 = (char4*)(g_aq1 + (size_t)t * CC);
    char4* d2 = (char4*)(g_aq2 + (size_t)t * CC);
#pragma unroll
    for (int g = 0; g < 6; g++) {
        char4 c1, c2;
        quant4(y[g], inv, c1, c2);
        d1[lane + 32 * g] = c1;
        d2[lane + 32 * g] = c2;
    }
}

// ---------------------------------------------------------------------------
// Weight prep: per-output-column max (parallel over k), then quantized
// transpose.
// ---------------------------------------------------------------------------
__global__ __launch_bounds__(256) void k_wmax(const float* __restrict__ w,
                                              int N, float* __restrict__ bsc) {
    __shared__ float red[8][33];
    int tx = threadIdx.x & 31, ks = threadIdx.x >> 5;
    int n = blockIdx.x * 32 + tx;
    float m = 0.0f;
    for (int k = ks; k < CC; k += 8)
        m = fmaxf(m, fabsf(w[(size_t)k * N + n]));
    red[ks][tx] = m;
    __syncthreads();
    if (ks == 0) {
        float v = red[0][tx];
#pragma unroll
        for (int i = 1; i < 8; i++) v = fmaxf(v, red[i][tx]);
        bsc[n] = fmaxf(v, 1e-30f) * (1.0f / 127.0f);
    }
}

__global__ __launch_bounds__(256) void k_wquant(const float* __restrict__ w,
                                                int N, const float* __restrict__ bsc,
                                                int8_t* __restrict__ q1,
                                                int8_t* __restrict__ q2) {
    __shared__ float t[32][33];
    int n0 = blockIdx.x * 32, k0 = blockIdx.y * 32;
    int tx = threadIdx.x & 31, ty = threadIdx.x >> 5;
    for (int i = ty; i < 32; i += 8) t[i][tx] = w[(size_t)(k0 + i) * N + n0 + tx];
    __syncthreads();
    for (int i = ty; i < 32; i += 8) {
        float v = t[tx][i];  // element (k0+tx, n0+i)
        int n = n0 + i;
        float inv = 1.0f / bsc[n];
        int a = __float2int_rn(v * inv);
        float r = fmaf(v, inv, -(float)a);
        int b = __float2int_rn(r * QSCL2);
        size_t o = (size_t)n * CC + k0 + tx;
        q1[o] = (int8_t)a;
        q2[o] = (int8_t)b;
    }
}

// ---------------------------------------------------------------------------
// INT8 IMMA GEMM: C[M,NT] = sa[m]*sb[n]*(accH + accM/254)
// CTA 64x128, BK=64, 3 stages, 2 CTAs/SM. 8 warps 2(M) x 4(N).
// Strength-reduced addressing: rotating stage pointers, incremental global
// src pointers, ldsm addresses = per-chunk base + compile-time immediate.
// ---------------------------------------------------------------------------
#define IBM 64
#define IBN 128
#define IBK 64
#define IPITCH 80
#define A_TILE (IBM * IPITCH)               // 5120
#define B_TILE (IBN * IPITCH)               // 10240
#define ISTAGE (2 * A_TILE + 2 * B_TILE)    // 30720
#define INSTG 3
#define IGSMEM (INSTG * ISTAGE)             // 92160 -> 2 CTAs/SM

template <int LDC_>
__global__ __launch_bounds__(256, 2) void k_gemm_i8(const int8_t* __restrict__ Bq1,
                                                    const int8_t* __restrict__ Bq2,
                                                    const float* __restrict__ bsc,
                                                    float* __restrict__ C) {
    extern __shared__ char dsm[];
    uint32_t sb = smem_u32(dsm);
    int tid = threadIdx.x, lane = tid & 31, wid = tid >> 5;
    int wm = wid >> 2, wn = wid & 3;          // 2 x 4 warp grid
    int bm = blockIdx.y * IBM, bn = blockIdx.x * IBN;
    const int kt = CC / IBK;                  // 12

    // ---- incremental cp.async pointers (advance by IBK per chunk) ----
    const int8_t* src[6];
    uint32_t doff[6];
    {
        int r0 = tid >> 2, sg = (tid & 3) * 16;
        src[0] = g_aq1 + (size_t)(bm + r0) * CC + sg;
        src[1] = g_aq2 + (size_t)(bm + r0) * CC + sg;
        src[2] = Bq1 + (size_t)(bn + r0) * CC + sg;
        src[3] = Bq1 + (size_t)(bn + r0 + 64) * CC + sg;
        src[4] = Bq2 + (size_t)(bn + r0) * CC + sg;
        src[5] = Bq2 + (size_t)(bn + r0 + 64) * CC + sg;
        uint32_t base = (uint32_t)(r0 * IPITCH + sg);
        doff[0] = base;
        doff[1] = base + A_TILE;
        doff[2] = base + 2 * A_TILE;
        doff[3] = base + 2 * A_TILE + 64 * IPITCH;
        doff[4] = base + 2 * A_TILE + B_TILE;
        doff[5] = base + 2 * A_TILE + B_TILE + 64 * IPITCH;
    }

    // ldsm per-warp base offsets (immediates added per unrolled instance)
    uint32_t abase = (uint32_t)((wm * 32 + (lane & 15)) * IPITCH +
                                ((lane >> 4) * 16));
    uint32_t bbase = (uint32_t)(2 * A_TILE + (wn * 32 + (lane & 15)) * IPITCH +
                                ((lane >> 4) * 16));

    int accH[2][4][4], accM[2][4][4];
#pragma unroll
    for (int i = 0; i < 2; i++)
#pragma unroll
        for (int j = 0; j < 4; j++)
#pragma unroll
            for (int r = 0; r < 4; r++) { accH[i][j][r] = 0; accM[i][j][r] = 0; }

    // prologue: chunks 0,1 into stages 0,1
#pragma unroll
    for (int pc = 0; pc < 2; pc++) {
        uint32_t stp = sb + pc * ISTAGE;
#pragma unroll
        for (int i = 0; i < 6; i++) {
            cpa16(stp + doff[i], src[i]);
            src[i] += IBK;
        }
        asm volatile("cp.async.commit_group;" ::: "memory");
    }

    uint32_t st = sb;                       // compute stage
    uint32_t stl = sb + 2 * ISTAGE;         // load stage (chunk c+2)
    const uint32_t send = sb + 3 * ISTAGE;

    for (int c = 0; c < kt; c++) {
        if (c + 1 < kt)
            asm volatile("cp.async.wait_group 1;" ::: "memory");
        else
            asm volatile("cp.async.wait_group 0;" ::: "memory");
        __syncthreads();   // chunk c visible; all warps past load stage

        if (c + 2 < kt) {
#pragma unroll
            for (int i = 0; i < 6; i++) {
                cpa16(stl + doff[i], src[i]);
                src[i] += IBK;
            }
            asm volatile("cp.async.commit_group;" ::: "memory");
            stl += ISTAGE;
            if (stl == send) stl = sb;
        }

        uint32_t sA = st + abase;
        uint32_t sB = st + bbase;
#pragma unroll
        for (int ks = 0; ks < 2; ks++) {
            uint32_t b1f[4][2], b2f[4][2];
#pragma unroll
            for (int p = 0; p < 2; p++) {
                uint32_t addr = sB + p * (16 * IPITCH) + ks * 32;
                uint32_t r[4];
                ldsm4(r, addr);
                b1f[2 * p][0] = r[0]; b1f[2 * p][1] = r[2];
                b1f[2 * p + 1][0] = r[1]; b1f[2 * p + 1][1] = r[3];
                ldsm4(r, addr + B_TILE);
                b2f[2 * p][0] = r[0]; b2f[2 * p][1] = r[2];
                b2f[2 * p + 1][0] = r[1]; b2f[2 * p + 1][1] = r[3];
            }
#pragma unroll
            for (int mt = 0; mt < 2; mt++) {
                uint32_t a1[4], a2[4];
                uint32_t aaddr = sA + mt * (16 * IPITCH) + ks * 32;
                ldsm4(a1, aaddr);
                ldsm4(a2, aaddr + A_TILE);
#pragma unroll
                for (int nt = 0; nt < 4; nt++) mma_s8(accH[mt][nt], a1, b1f[nt]);
#pragma unroll
                for (int nt = 0; nt < 4; nt++) mma_s8(accM[mt][nt], a1, b2f[nt]);
#pragma unroll
                for (int nt = 0; nt < 4; nt++) mma_s8(accM[mt][nt], a2, b1f[nt]);
            }
        }
        st += ISTAGE;
        if (st == send) st = sb;
    }

    // epilogue: dequantize and store fp32
#pragma unroll
    for (int mt = 0; mt < 2; mt++) {
        int r0 = bm + wm * 32 + mt * 16 + (lane >> 2);
        float sa0 = g_asc[r0], sa1 = g_asc[r0 + 8];
#pragma unroll
        for (int nt = 0; nt < 4; nt++) {
            int cidx = bn + wn * 32 + nt * 8 + (lane & 3) * 2;
            float sb0 = bsc[cidx], sb1 = bsc[cidx + 1];
            const int* h = accH[mt][nt];
            const int* m = accM[mt][nt];
            float v00 = sa0 * sb0 * ((float)h[0] + (float)m[0] * (1.0f / QSCL2));
            float v01 = sa0 * sb1 * ((float)h[1] + (float)m[1] * (1.0f / QSCL2));
            float v10 = sa1 * sb0 * ((float)h[2] + (float)m[2] * (1.0f / QSCL2));
            float v11 = sa1 * sb1 * ((float)h[3] + (float)m[3] * (1.0f / QSCL2));
            *(float2*)(C + (size_t)r0 * LDC_ + cidx) = make_float2(v00, v01);
            *(float2*)(C + (size_t)(r0 + 8) * LDC_ + cidx) = make_float2(v10, v11);
        }
    }
}

// ---------------------------------------------------------------------------
// warp-per-token inverse L2 norm of k. No barriers.
// ---------------------------------------------------------------------------
__global__ __launch_bounds__(256) void k_norms() {
    int lane = threadIdx.x & 31;
    int t = blockIdx.x * 8 + (threadIdx.x >> 5);
    const float4* krow = (const float4*)(g_qkv + (size_t)t * QKVD + EE);
    float sk = 0.f;
#pragma unroll
    for (int g = 0; g < 6; g++) {
        float4 k = krow[lane + 32 * g];
        sk += k.x * k.x + k.y * k.y + k.z * k.z + k.w * k.w;
    }
    sk = warp_sum(sk);
    if (lane == 0) g_kinv[t] = 1.0f / fmaxf(sqrtf(sk), 1e-12f);
}

// ---------------------------------------------------------------------------
// kv partial sums: kv[b,e] = sum_t phi_k[t,e] * v[t,e]. 64 chunks x 8 batches.
// ---------------------------------------------------------------------------
__global__ __launch_bounds__(256) void k_kvred() {
    int b = blockIdx.y;
    int chunk = blockIdx.x;  // 0..KVCH-1
    int tid = threadIdx.x;
    float a0 = 0.f, a1 = 0.f, a2 = 0.f;
    int t0 = b * NN + chunk * (NN / KVCH);
#pragma unroll 2
    for (int i = 0; i < NN / KVCH; i++) {
        const float* row = g_qkv + (size_t)(t0 + i) * QKVD;
        const float* kr = row + EE;
        const float* vr = row + 2 * EE;
        float ki = g_kinv[t0 + i];
        a0 += (kr[tid] * ki) * vr[tid];
        a1 += (kr[tid + 256] * ki) * vr[tid + 256];
        a2 += (kr[tid + 512] * ki) * vr[tid + 512];
    }
    float* dst = g_kvpart + ((size_t)chunk * BQ + b) * EE;
    dst[tid] = a0; dst[tid + 256] = a1; dst[tid + 512] = a2;
}

__global__ __launch_bounds__(256) void k_kvsum() {
    int i = blockIdx.x * 256 + threadIdx.x;
    float s = 0.f;
#pragma unroll
    for (int c = 0; c < KVCH; c++) s += g_kvpart[(size_t)c * BQ * EE + i];
    g_kv[i] = s;
}

// ---------------------------------------------------------------------------
// warp-per-token: qinv, attn = phi_q*kv, layernorm, int8 quant. No barriers.
// ---------------------------------------------------------------------------
__global__ __launch_bounds__(256) void k_attn_ln(const float* __restrict__ gam,
                                                 const float* __restrict__ bet) {
    int lane = threadIdx.x & 31;
    int t = blockIdx.x * 8 + (threadIdx.x >> 5);
    int b = t >> 12;
    const float4* qrow = (const float4*)(g_qkv + (size_t)t * QKVD);
    const float4* kvb = (const float4*)(g_kv + b * EE);
    const float4* g4 = (const float4*)gam;
    const float4* b4 = (const float4*)bet;

    float4 q[6];
    float qsq = 0.f;
#pragma unroll
    for (int g = 0; g < 6; g++) {
        q[g] = qrow[lane + 32 * g];
        qsq += q[g].x * q[g].x + q[g].y * q[g].y + q[g].z * q[g].z + q[g].w * q[g].w;
    }
    qsq = warp_sum(qsq);
    float qi = 1.0f / fmaxf(sqrtf(qsq), 1e-12f);

    float a[6][4];
    float s = 0.f, sq = 0.f;
#pragma unroll
    for (int g = 0; g < 6; g++) {
        float4 kv = kvb[lane + 32 * g];
        a[g][0] = (q[g].x * qi) * kv.x;
        a[g][1] = (q[g].y * qi) * kv.y;
        a[g][2] = (q[g].z * qi) * kv.z;
        a[g][3] = (q[g].w * qi) * kv.w;
#pragma unroll
        for (int e = 0; e < 4; e++) { s += a[g][e]; sq += a[g][e] * a[g][e]; }
    }
    s = warp_sum(s);
    sq = warp_sum(sq);
    float mu = s * (1.0f / EE);
    float rstd = rsqrtf(sq * (1.0f / EE) - mu * mu + 1e-5f);

    float y[6][4];
    float m = 0.f;
#pragma unroll
    for (int g = 0; g < 6; g++) {
        float4 gg = g4[lane + 32 * g], bb = b4[lane + 32 * g];
        y[g][0] = (a[g][0] - mu) * rstd * gg.x + bb.x;
        y[g][1] = (a[g][1] - mu) * rstd * gg.y + bb.y;
        y[g][2] = (a[g][2] - mu) * rstd * gg.z + bb.z;
        y[g][3] = (a[g][3] - mu) * rstd * gg.w + bb.w;
#pragma unroll
        for (int e = 0; e < 4; e++) m = fmaxf(m, fabsf(y[g][e]));
    }
    m = warp_max(m);
    float sa = fmaxf(m, 1e-30f) * (1.0f / 127.0f);
    float inv = 1.0f / sa;
    if (lane == 0) g_asc[t] = sa;

    char4* d1 = (char4*)(g_aq1 + (size_t)t * EE);
    char4* d2 = (char4*)(g_aq2 + (size_t)t * EE);
#pragma unroll
    for (int g = 0; g < 6; g++) {
        char4 c1, c2;
        quant4(y[g], inv, c1, c2);
        d1[lane + 32 * g] = c1;
        d2[lane + 32 * g] = c2;
    }
}

// ---------------------------------------------------------------------------
extern "C" void kernel_launch(void* const* d_in, const int* in_sizes, int n_in,
                              void* d_out, int out_size) {
    const float* x        = (const float*)d_in[0];
    const float* w_qkv    = (const float*)d_in[1];
    const float* w_proj   = (const float*)d_in[2];
    const float* ln_in_g  = (const float*)d_in[3];
    const float* ln_in_b  = (const float*)d_in[4];
    const float* ln_out_g = (const float*)d_in[5];
    const float* ln_out_b = (const float*)d_in[6];
    float* out = (float*)d_out;

    cudaFuncSetAttribute(k_gemm_i8<QKVD>, cudaFuncAttributeMaxDynamicSharedMemorySize, IGSMEM);
    cudaFuncSetAttribute(k_gemm_i8<CC>, cudaFuncAttributeMaxDynamicSharedMemorySize, IGSMEM);

    int8_t* bq1q; cudaGetSymbolAddress((void**)&bq1q, g_bq1q);
    int8_t* bq2q; cudaGetSymbolAddress((void**)&bq2q, g_bq2q);
    float*  bscq; cudaGetSymbolAddress((void**)&bscq, g_bscq);
    int8_t* bq1p; cudaGetSymbolAddress((void**)&bq1p, g_bq1p);
    int8_t* bq2p; cudaGetSymbolAddress((void**)&bq2p, g_bq2p);
    float*  bscp; cudaGetSymbolAddress((void**)&bscp, g_bscp);
    float*  qkv;  cudaGetSymbolAddress((void**)&qkv, g_qkv);

    // order chosen so k_gemm_i8<QKVD> is the 4th launch (ncu -s captures it)
    k_ln_in<<<MM / 8, 256>>>(x, ln_in_g, ln_in_b);
    k_wmax<<<QKVD / 32, 256>>>(w_qkv, QKVD, bscq);
    k_wquant<<<dim3(QKVD / 32, CC / 32), 256>>>(w_qkv, QKVD, bscq, bq1q, bq2q);
    k_gemm_i8<QKVD><<<dim3(QKVD / IBN, MM / IBM), 256, IGSMEM>>>(bq1q, bq2q, bscq, qkv);
    k_norms<<<MM / 8, 256>>>();
    k_kvred<<<dim3(KVCH, BQ), 256>>>();
    k_kvsum<<<BQ * EE / 256, 256>>>();
    k_attn_ln<<<MM / 8, 256>>>(ln_out_g, ln_out_b);
    k_wmax<<<CC / 32, 256>>>(w_proj, CC, bscp);
    k_wquant<<<dim3(CC / 32, CC / 32), 256>>>(w_proj, CC, bscp, bq1p, bq2p);
    k_gemm_i8<CC><<<dim3(CC / IBN, MM / IBM), 256, IGSMEM>>>(bq1p, bq2p, bscp, out);
}

// round 15
// speedup vs baseline: 1.1031x; 1.1031x over previous
#include <cuda_runtime.h>
#include <cuda_bf16.h>
#include <cstdint>

// Problem constants
#define BQ 8
#define NN 4096
#define CC 768
#define EE 768
#define MM (BQ * NN)     // 32768 tokens
#define QKVD (3 * EE)    // 2304
#define KVCH 64          // kv reduction chunks per batch

// ---------------- device scratch (no allocation allowed) -------------------
__device__ __align__(128) float  g_qkv[(size_t)MM * QKVD];    // GEMM1 out fp32
__device__ __align__(128) int8_t g_aq1[(size_t)MM * CC];      // A quant level 1
__device__ __align__(128) int8_t g_aq2[(size_t)MM * CC];      // A quant level 2
__device__ __align__(128) float  g_asc[MM];                   // A row scales
__device__ __align__(128) int8_t g_bq1q[(size_t)QKVD * CC];   // w_qkv^T q1 [2304,768]
__device__ __align__(128) int8_t g_bq2q[(size_t)QKVD * CC];
__device__ __align__(128) float  g_bscq[QKVD];
__device__ __align__(128) int8_t g_bq1p[(size_t)EE * CC];     // w_proj^T q1 [768,768]
__device__ __align__(128) int8_t g_bq2p[(size_t)EE * CC];
__device__ __align__(128) float  g_bscp[EE];
__device__ float g_kvpart[KVCH * BQ * EE];
__device__ float g_kv[BQ * EE];
__device__ float g_kinv[MM];

#define QSCL2 254.0f

// ---------------------------- helpers --------------------------------------
__device__ __forceinline__ uint32_t smem_u32(const void* p) {
    uint32_t a;
    asm("{ .reg .u64 t; cvta.to.shared.u64 t, %1; cvt.u32.u64 %0, t; }"
        : "=r"(a) : "l"(p));
    return a;
}
__device__ __forceinline__ void cpa16(uint32_t dst, const void* src) {
    asm volatile("cp.async.cg.shared.global [%0], [%1], 16;" :: "r"(dst), "l"(src));
}
__device__ __forceinline__ void ldsm4(uint32_t* r, uint32_t addr) {
    asm volatile("ldmatrix.sync.aligned.m8n8.x4.shared.b16 {%0,%1,%2,%3}, [%4];"
                 : "=r"(r[0]), "=r"(r[1]), "=r"(r[2]), "=r"(r[3]) : "r"(addr));
}
__device__ __forceinline__ void mma_s8(int* d, const uint32_t* a,
                                       const uint32_t* b) {
    asm volatile(
        "mma.sync.aligned.m16n8k32.row.col.s32.s8.s8.s32 "
        "{%0,%1,%2,%3},{%4,%5,%6,%7},{%8,%9},{%0,%1,%2,%3};"
        : "+r"(d[0]), "+r"(d[1]), "+r"(d[2]), "+r"(d[3])
        : "r"(a[0]), "r"(a[1]), "r"(a[2]), "r"(a[3]), "r"(b[0]), "r"(b[1]));
}

// warp butterfly reductions: every lane gets the result; no barriers
__device__ __forceinline__ float warp_sum(float v) {
#pragma unroll
    for (int o = 16; o > 0; o >>= 1) v += __shfl_xor_sync(0xffffffffu, v, o);
    return v;
}
__device__ __forceinline__ float warp_max(float v) {
#pragma unroll
    for (int o = 16; o > 0; o >>= 1)
        v = fmaxf(v, __shfl_xor_sync(0xffffffffu, v, o));
    return v;
}

// quantize 4 values -> two char4 (levels 1 and 2)
__device__ __forceinline__ void quant4(const float* y, float inv,
                                       char4& c1, char4& c2) {
    int q1[4], q2[4];
#pragma unroll
    for (int e = 0; e < 4; e++) {
        q1[e] = __float2int_rn(y[e] * inv);
        float r = fmaf(y[e], inv, -(float)q1[e]);
        q2[e] = __float2int_rn(r * QSCL2);
    }
    c1 = make_char4((char)q1[0], (char)q1[1], (char)q1[2], (char)q1[3]);
    c2 = make_char4((char)q2[0], (char)q2[1], (char)q2[2], (char)q2[3]);
}

// ---------------------------------------------------------------------------
// Kernel 1: warp-per-token layernorm(x) + int8 2-level quant. No barriers.
// ---------------------------------------------------------------------------
__global__ __launch_bounds__(256) void k_ln_in(const float* __restrict__ x,
                                               const float* __restrict__ gam,
                                               const float* __restrict__ bet) {
    int lane = threadIdx.x & 31;
    int t = blockIdx.x * 8 + (threadIdx.x >> 5);
    const float4* row = (const float4*)(x + (size_t)t * CC);
    const float4* g4 = (const float4*)gam;
    const float4* b4 = (const float4*)bet;

    float4 v[6];
    float s = 0.f, sq = 0.f;
#pragma unroll
    for (int g = 0; g < 6; g++) {
        v[g] = row[lane + 32 * g];
        s += v[g].x + v[g].y + v[g].z + v[g].w;
        sq += v[g].x * v[g].x + v[g].y * v[g].y + v[g].z * v[g].z + v[g].w * v[g].w;
    }
    s = warp_sum(s);
    sq = warp_sum(sq);
    float mu = s * (1.0f / CC);
    float rstd = rsqrtf(sq * (1.0f / CC) - mu * mu + 1e-5f);

    float y[6][4];
    float m = 0.f;
#pragma unroll
    for (int g = 0; g < 6; g++) {
        float4 gg = g4[lane + 32 * g], bb = b4[lane + 32 * g];
        y[g][0] = (v[g].x - mu) * rstd * gg.x + bb.x;
        y[g][1] = (v[g].y - mu) * rstd * gg.y + bb.y;
        y[g][2] = (v[g].z - mu) * rstd * gg.z + bb.z;
        y[g][3] = (v[g].w - mu) * rstd * gg.w + bb.w;
#pragma unroll
        for (int e = 0; e < 4; e++) m = fmaxf(m, fabsf(y[g][e]));
    }
    m = warp_max(m);
    float sa = fmaxf(m, 1e-30f) * (1.0f / 127.0f);
    float inv = 1.0f / sa;
    if (lane == 0) g_asc[t] = sa;

    char4* d1 = (char4*)(g_aq1 + (size_t)t * CC);
    char4* d2 = (char4*)(g_aq2 + (size_t)t * CC);
#pragma unroll
    for (int g = 0; g < 6; g++) {
        char4 c1, c2;
        quant4(y[g], inv, c1, c2);
        d1[lane + 32 * g] = c1;
        d2[lane + 32 * g] = c2;
    }
}

// ---------------------------------------------------------------------------
// Weight prep: per-output-column max (parallel over k), then quantized
// transpose.
// ---------------------------------------------------------------------------
__global__ __launch_bounds__(256) void k_wmax(const float* __restrict__ w,
                                              int N, float* __restrict__ bsc) {
    __shared__ float red[8][33];
    int tx = threadIdx.x & 31, ks = threadIdx.x >> 5;
    int n = blockIdx.x * 32 + tx;
    float m = 0.0f;
    for (int k = ks; k < CC; k += 8)
        m = fmaxf(m, fabsf(w[(size_t)k * N + n]));
    red[ks][tx] = m;
    __syncthreads();
    if (ks == 0) {
        float v = red[0][tx];
#pragma unroll
        for (int i = 1; i < 8; i++) v = fmaxf(v, red[i][tx]);
        bsc[n] = fmaxf(v, 1e-30f) * (1.0f / 127.0f);
    }
}

__global__ __launch_bounds__(256) void k_wquant(const float* __restrict__ w,
                                                int N, const float* __restrict__ bsc,
                                                int8_t* __restrict__ q1,
                                                int8_t* __restrict__ q2) {
    __shared__ float t[32][33];
    int n0 = blockIdx.x * 32, k0 = blockIdx.y * 32;
    int tx = threadIdx.x & 31, ty = threadIdx.x >> 5;
    for (int i = ty; i < 32; i += 8) t[i][tx] = w[(size_t)(k0 + i) * N + n0 + tx];
    __syncthreads();
    for (int i = ty; i < 32; i += 8) {
        float v = t[tx][i];  // element (k0+tx, n0+i)
        int n = n0 + i;
        float inv = 1.0f / bsc[n];
        int a = __float2int_rn(v * inv);
        float r = fmaf(v, inv, -(float)a);
        int b = __float2int_rn(r * QSCL2);
        size_t o = (size_t)n * CC + k0 + tx;
        q1[o] = (int8_t)a;
        q2[o] = (int8_t)b;
    }
}

// ---------------------------------------------------------------------------
// INT8 IMMA GEMM: C[M,NT] = sa[m]*sb[n]*(accH + accM/254)
// CTA 64x128, BK=128 (full chunk), 2 stages, 2 CTAs/SM. 8 warps 2(M) x 4(N).
// Rows pitch 144B -> conflict-free ldmatrix (start bank 4r mod 32).
// 96 MMAs per warp per barrier interval (2x R13) -> amortize sync overhead.
// ---------------------------------------------------------------------------
#define IBM 64
#define IBN 128
#define IBK 128
#define IPITCH 144
#define A_TILE (IBM * IPITCH)               // 9216
#define B_TILE (IBN * IPITCH)               // 18432
#define ISTAGE (2 * A_TILE + 2 * B_TILE)    // 55296
#define IGSMEM (2 * ISTAGE)                 // 110592 -> 2 CTAs/SM (216KB)

template <int ROWS>
__device__ __forceinline__ void load_i8_tile(uint32_t dst,
                                             const int8_t* __restrict__ g,
                                             int row0, int kc, int tid) {
#pragma unroll
    for (int i = 0; i < ROWS / 32; i++) {
        int idx = tid + i * 256;
        int r = idx >> 3, seg = idx & 7;
        cpa16(dst + (uint32_t)(r * IPITCH + seg * 16),
              g + (size_t)(row0 + r) * CC + kc + seg * 16);
    }
}

__device__ __forceinline__ void load_chunk_i8(uint32_t st, int bm, int bn, int kc,
                                              int tid, const int8_t* Bq1,
                                              const int8_t* Bq2) {
    load_i8_tile<64>(st,                        g_aq1, bm, kc, tid);
    load_i8_tile<64>(st + A_TILE,               g_aq2, bm, kc, tid);
    load_i8_tile<128>(st + 2 * A_TILE,          Bq1,   bn, kc, tid);
    load_i8_tile<128>(st + 2 * A_TILE + B_TILE, Bq2,   bn, kc, tid);
}

template <int LDC_>
__global__ __launch_bounds__(256, 2) void k_gemm_i8(const int8_t* __restrict__ Bq1,
                                                    const int8_t* __restrict__ Bq2,
                                                    const float* __restrict__ bsc,
                                                    float* __restrict__ C) {
    extern __shared__ char dsm[];
    uint32_t sb = smem_u32(dsm);
    int tid = threadIdx.x, lane = tid & 31, wid = tid >> 5;
    int wm = wid >> 2, wn = wid & 3;          // 2 x 4 warp grid
    int bm = blockIdx.y * IBM, bn = blockIdx.x * IBN;
    const int kt = CC / IBK;                  // 6 chunks

    uint32_t lrow = (uint32_t)(lane & 15);
    uint32_t lboff = (uint32_t)((lane >> 4) * 16);
    uint32_t abase = (uint32_t)((wm * 32 + lrow) * IPITCH) + lboff;
    uint32_t bbase = (uint32_t)(2 * A_TILE + (wn * 32 + lrow) * IPITCH) + lboff;

    int accH[2][4][4], accM[2][4][4];
#pragma unroll
    for (int i = 0; i < 2; i++)
#pragma unroll
        for (int j = 0; j < 4; j++)
#pragma unroll
            for (int r = 0; r < 4; r++) { accH[i][j][r] = 0; accM[i][j][r] = 0; }

    // prologue: chunk 0 into stage 0
    load_chunk_i8(sb, bm, bn, 0, tid, Bq1, Bq2);
    asm volatile("cp.async.commit_group;" ::: "memory");

    for (int c = 0; c < kt; c++) {
        asm volatile("cp.async.wait_group 0;" ::: "memory");
        __syncthreads();   // chunk c visible; all warps past stage (c+1)&1

        if (c + 1 < kt) {
            load_chunk_i8(sb + ((c + 1) & 1) * ISTAGE, bm, bn, (c + 1) * IBK,
                          tid, Bq1, Bq2);
            asm volatile("cp.async.commit_group;" ::: "memory");
        }

        uint32_t st = sb + (c & 1) * ISTAGE;
        uint32_t sA = st + abase;
        uint32_t sB = st + bbase;
#pragma unroll
        for (int ks = 0; ks < 4; ks++) {
            uint32_t b1f[4][2], b2f[4][2];
#pragma unroll
            for (int p = 0; p < 2; p++) {
                uint32_t addr = sB + p * (16 * IPITCH) + ks * 32;
                uint32_t r[4];
                ldsm4(r, addr);
                b1f[2 * p][0] = r[0]; b1f[2 * p][1] = r[2];
                b1f[2 * p + 1][0] = r[1]; b1f[2 * p + 1][1] = r[3];
                ldsm4(r, addr + B_TILE);
                b2f[2 * p][0] = r[0]; b2f[2 * p][1] = r[2];
                b2f[2 * p + 1][0] = r[1]; b2f[2 * p + 1][1] = r[3];
            }
#pragma unroll
            for (int mt = 0; mt < 2; mt++) {
                uint32_t a1[4], a2[4];
                uint32_t aaddr = sA + mt * (16 * IPITCH) + ks * 32;
                ldsm4(a1, aaddr);
                ldsm4(a2, aaddr + A_TILE);
#pragma unroll
                for (int nt = 0; nt < 4; nt++) mma_s8(accH[mt][nt], a1, b1f[nt]);
#pragma unroll
                for (int nt = 0; nt < 4; nt++) mma_s8(accM[mt][nt], a1, b2f[nt]);
#pragma unroll
                for (int nt = 0; nt < 4; nt++) mma_s8(accM[mt][nt], a2, b1f[nt]);
            }
        }
    }

    // epilogue: dequantize and store fp32
#pragma unroll
    for (int mt = 0; mt < 2; mt++) {
        int r0 = bm + wm * 32 + mt * 16 + (lane >> 2);
        float sa0 = g_asc[r0], sa1 = g_asc[r0 + 8];
#pragma unroll
        for (int nt = 0; nt < 4; nt++) {
            int cidx = bn + wn * 32 + nt * 8 + (lane & 3) * 2;
            float sb0 = bsc[cidx], sb1 = bsc[cidx + 1];
            const int* h = accH[mt][nt];
            const int* m = accM[mt][nt];
            float v00 = sa0 * sb0 * ((float)h[0] + (float)m[0] * (1.0f / QSCL2));
            float v01 = sa0 * sb1 * ((float)h[1] + (float)m[1] * (1.0f / QSCL2));
            float v10 = sa1 * sb0 * ((float)h[2] + (float)m[2] * (1.0f / QSCL2));
            float v11 = sa1 * sb1 * ((float)h[3] + (float)m[3] * (1.0f / QSCL2));
            *(float2*)(C + (size_t)r0 * LDC_ + cidx) = make_float2(v00, v01);
            *(float2*)(C + (size_t)(r0 + 8) * LDC_ + cidx) = make_float2(v10, v11);
        }
    }
}

// ---------------------------------------------------------------------------
// warp-per-token inverse L2 norm of k. No barriers.
// ---------------------------------------------------------------------------
__global__ __launch_bounds__(256) void k_norms() {
    int lane = threadIdx.x & 31;
    int t = blockIdx.x * 8 + (threadIdx.x >> 5);
    const float4* krow = (const float4*)(g_qkv + (size_t)t * QKVD + EE);
    float sk = 0.f;
#pragma unroll
    for (int g = 0; g < 6; g++) {
        float4 k = krow[lane + 32 * g];
        sk += k.x * k.x + k.y * k.y + k.z * k.z + k.w * k.w;
    }
    sk = warp_sum(sk);
    if (lane == 0) g_kinv[t] = 1.0f / fmaxf(sqrtf(sk), 1e-12f);
}

// ---------------------------------------------------------------------------
// kv partial sums: kv[b,e] = sum_t phi_k[t,e] * v[t,e]. 64 chunks x 8 batches.
// ---------------------------------------------------------------------------
__global__ __launch_bounds__(256) void k_kvred() {
    int b = blockIdx.y;
    int chunk = blockIdx.x;  // 0..KVCH-1
    int tid = threadIdx.x;
    float a0 = 0.f, a1 = 0.f, a2 = 0.f;
    int t0 = b * NN + chunk * (NN / KVCH);
#pragma unroll 2
    for (int i = 0; i < NN / KVCH; i++) {
        const float* row = g_qkv + (size_t)(t0 + i) * QKVD;
        const float* kr = row + EE;
        const float* vr = row + 2 * EE;
        float ki = g_kinv[t0 + i];
        a0 += (kr[tid] * ki) * vr[tid];
        a1 += (kr[tid + 256] * ki) * vr[tid + 256];
        a2 += (kr[tid + 512] * ki) * vr[tid + 512];
    }
    float* dst = g_kvpart + ((size_t)chunk * BQ + b) * EE;
    dst[tid] = a0; dst[tid + 256] = a1; dst[tid + 512] = a2;
}

__global__ __launch_bounds__(256) void k_kvsum() {
    int i = blockIdx.x * 256 + threadIdx.x;
    float s = 0.f;
#pragma unroll
    for (int c = 0; c < KVCH; c++) s += g_kvpart[(size_t)c * BQ * EE + i];
    g_kv[i] = s;
}

// ---------------------------------------------------------------------------
// warp-per-token: qinv, attn = phi_q*kv, layernorm, int8 quant. No barriers.
// ---------------------------------------------------------------------------
__global__ __launch_bounds__(256) void k_attn_ln(const float* __restrict__ gam,
                                                 const float* __restrict__ bet) {
    int lane = threadIdx.x & 31;
    int t = blockIdx.x * 8 + (threadIdx.x >> 5);
    int b = t >> 12;
    const float4* qrow = (const float4*)(g_qkv + (size_t)t * QKVD);
    const float4* kvb = (const float4*)(g_kv + b * EE);
    const float4* g4 = (const float4*)gam;
    const float4* b4 = (const float4*)bet;

    float4 q[6];
    float qsq = 0.f;
#pragma unroll
    for (int g = 0; g < 6; g++) {
        q[g] = qrow[lane + 32 * g];
        qsq += q[g].x * q[g].x + q[g].y * q[g].y + q[g].z * q[g].z + q[g].w * q[g].w;
    }
    qsq = warp_sum(qsq);
    float qi = 1.0f / fmaxf(sqrtf(qsq), 1e-12f);

    float a[6][4];
    float s = 0.f, sq = 0.f;
#pragma unroll
    for (int g = 0; g < 6; g++) {
        float4 kv = kvb[lane + 32 * g];
        a[g][0] = (q[g].x * qi) * kv.x;
        a[g][1] = (q[g].y * qi) * kv.y;
        a[g][2] = (q[g].z * qi) * kv.z;
        a[g][3] = (q[g].w * qi) * kv.w;
#pragma unroll
        for (int e = 0; e < 4; e++) { s += a[g][e]; sq += a[g][e] * a[g][e]; }
    }
    s = warp_sum(s);
    sq = warp_sum(sq);
    float mu = s * (1.0f / EE);
    float rstd = rsqrtf(sq * (1.0f / EE) - mu * mu + 1e-5f);

    float y[6][4];
    float m = 0.f;
#pragma unroll
    for (int g = 0; g < 6; g++) {
        float4 gg = g4[lane + 32 * g], bb = b4[lane + 32 * g];
        y[g][0] = (a[g][0] - mu) * rstd * gg.x + bb.x;
        y[g][1] = (a[g][1] - mu) * rstd * gg.y + bb.y;
        y[g][2] = (a[g][2] - mu) * rstd * gg.z + bb.z;
        y[g][3] = (a[g][3] - mu) * rstd * gg.w + bb.w;
#pragma unroll
        for (int e = 0; e < 4; e++) m = fmaxf(m, fabsf(y[g][e]));
    }
    m = warp_max(m);
    float sa = fmaxf(m, 1e-30f) * (1.0f / 127.0f);
    float inv = 1.0f / sa;
    if (lane == 0) g_asc[t] = sa;

    char4* d1 = (char4*)(g_aq1 + (size_t)t * EE);
    char4* d2 = (char4*)(g_aq2 + (size_t)t * EE);
#pragma unroll
    for (int g = 0; g < 6; g++) {
        char4 c1, c2;
        quant4(y[g], inv, c1, c2);
        d1[lane + 32 * g] = c1;
        d2[lane + 32 * g] = c2;
    }
}

// ---------------------------------------------------------------------------
extern "C" void kernel_launch(void* const* d_in, const int* in_sizes, int n_in,
                              void* d_out, int out_size) {
    const float* x        = (const float*)d_in[0];
    const float* w_qkv    = (const float*)d_in[1];
    const float* w_proj   = (const float*)d_in[2];
    const float* ln_in_g  = (const float*)d_in[3];
    const float* ln_in_b  = (const float*)d_in[4];
    const float* ln_out_g = (const float*)d_in[5];
    const float* ln_out_b = (const float*)d_in[6];
    float* out = (float*)d_out;

    cudaFuncSetAttribute(k_gemm_i8<QKVD>, cudaFuncAttributeMaxDynamicSharedMemorySize, IGSMEM);
    cudaFuncSetAttribute(k_gemm_i8<CC>, cudaFuncAttributeMaxDynamicSharedMemorySize, IGSMEM);

    int8_t* bq1q; cudaGetSymbolAddress((void**)&bq1q, g_bq1q);
    int8_t* bq2q; cudaGetSymbolAddress((void**)&bq2q, g_bq2q);
    float*  bscq; cudaGetSymbolAddress((void**)&bscq, g_bscq);
    int8_t* bq1p; cudaGetSymbolAddress((void**)&bq1p, g_bq1p);
    int8_t* bq2p; cudaGetSymbolAddress((void**)&bq2p, g_bq2p);
    float*  bscp; cudaGetSymbolAddress((void**)&bscp, g_bscp);
    float*  qkv;  cudaGetSymbolAddress((void**)&qkv, g_qkv);

    // order chosen so k_gemm_i8<QKVD> is the 4th launch (ncu -s captures it)
    k_ln_in<<<MM / 8, 256>>>(x, ln_in_g, ln_in_b);
    k_wmax<<<QKVD / 32, 256>>>(w_qkv, QKVD, bscq);
    k_wquant<<<dim3(QKVD / 32, CC / 32), 256>>>(w_qkv, QKVD, bscq, bq1q, bq2q);
    k_gemm_i8<QKVD><<<dim3(QKVD / IBN, MM / IBM), 256, IGSMEM>>>(bq1q, bq2q, bscq, qkv);
    k_norms<<<MM / 8, 256>>>();
    k_kvred<<<dim3(KVCH, BQ), 256>>>();
    k_kvsum<<<BQ * EE / 256, 256>>>();
    k_attn_ln<<<MM / 8, 256>>>(ln_out_g, ln_out_b);
    k_wmax<<<CC / 32, 256>>>(w_proj, CC, bscp);
    k_wquant<<<dim3(CC / 32, CC / 32), 256>>>(w_proj, CC, bscp, bq1p, bq2p);
    k_gemm_i8<CC><<<dim3(CC / IBN, MM / IBM), 256, IGSMEM>>>(bq1p, bq2p, bscp, out);
}